// round 6
// baseline (speedup 1.0000x reference)
#include <cuda_runtime.h>

#define RL  132     // padded smem row length (floats)
#define NP  128     // particles per event
#define UN  128     // hidden units
#define NHID 6
#define NTHREADS 512

// smem layout (floats):
//   Xs  [128][RL]  : xT (unit-major activations)   (also transpose staging early)
//   Ys  [128][RL]  : y  (particle-major dense out) (also x0T early, partials late)
//   AD  [128][RL]  : adjT  (AD[n][i] = adj[i][n])
//   WS  [2][16][128] : W chunk double buffer
//   MSK [128], RED[8] (RED[7] = denom)
#define SMEM_FLOATS (3 * NP * RL + 2 * 16 * UN + NP + 8)
#define SMEM_BYTES  (SMEM_FLOATS * 4)

__device__ __forceinline__ unsigned long long ffma2(unsigned long long a,
                                                    unsigned long long b,
                                                    unsigned long long c) {
    unsigned long long d;
    asm("fma.rn.f32x2 %0, %1, %2, %3;" : "=l"(d) : "l"(a), "l"(b), "l"(c));
    return d;
}

__device__ __forceinline__ unsigned long long pack2(float x) {
    unsigned long long d;
    asm("mov.b64 %0, {%1, %1};" : "=l"(d) : "f"(x));
    return d;
}

__device__ __forceinline__ float2 unpack2(unsigned long long v) {
    float2 f;
    asm("mov.b64 {%0, %1}, %2;" : "=f"(f.x), "=f"(f.y) : "l"(v));
    return f;
}

// One k-step of the 8i x 4j per-thread microkernel.
// C[i][j] += As[k][i] * Bs[k][j]
// A loaded as natural f32x2 pairs along i (no pack), B scalars packed (4 movs).
// acc[jj][p]: jj = j0+jj, p = i-pair (i0+2p, i0+2p+1)
__device__ __forceinline__ void mk_step(const float* __restrict__ As, int as,
                                        const float* __restrict__ Bs, int bs,
                                        int k, int i0, int j0,
                                        unsigned long long acc[4][4]) {
    ulonglong2 aq0 = *(const ulonglong2*)(As + k * as + i0);
    ulonglong2 aq1 = *(const ulonglong2*)(As + k * as + i0 + 4);
    float4 bv = *(const float4*)(Bs + k * bs + j0);
    unsigned long long ap[4] = {aq0.x, aq0.y, aq1.x, aq1.y};
    float bsc[4] = {bv.x, bv.y, bv.z, bv.w};
#pragma unroll
    for (int jj = 0; jj < 4; ++jj) {
        unsigned long long bp = pack2(bsc[jj]);
#pragma unroll
        for (int p = 0; p < 4; ++p) acc[jj][p] = ffma2(ap[p], bp, acc[jj][p]);
    }
}

__device__ __forceinline__ void zero_acc(unsigned long long acc[4][4]) {
#pragma unroll
    for (int jj = 0; jj < 4; ++jj)
#pragma unroll
        for (int p = 0; p < 4; ++p) acc[jj][p] = 0ull;
}

__global__ __launch_bounds__(NTHREADS, 1)
void gcn_fused_kernel(const int* __restrict__ pdg,
                      const float* __restrict__ feat,
                      const float* __restrict__ adj,
                      const float* __restrict__ mask,
                      const float* __restrict__ emb,
                      const float* __restrict__ W_in,
                      const float* __restrict__ b_in,
                      const float* __restrict__ W_h,
                      const float* __restrict__ b_h,
                      const float* __restrict__ W_out,
                      const float* __restrict__ b_out,
                      float* __restrict__ out)
{
    extern __shared__ float sm[];
    float* Xs  = sm;
    float* Ys  = Xs + NP * RL;
    float* AD  = Ys + NP * RL;
    float* WS  = AD + NP * RL;          // 2 * 16 * 128 floats
    float* MSK = WS + 2 * 16 * UN;      // 128
    float* RED = MSK + NP;              // 8 (RED[7] = denom)

    const int b    = blockIdx.x;
    const int tid  = threadIdx.x;
    const int lane = tid & 31;
    const int warp = tid >> 5;          // 0..15

    // 16 warps in 4x4 grid, each warp covers 32i x 32j.
    // within warp: 4 ty x 8 tx; per-thread tile 8i x 4j.
    const int warpY = warp >> 2;                 // 0..3
    const int warpX = warp & 3;                  // 0..3
    const int ty = lane >> 3;                    // 0..3
    const int tx = lane & 7;                     // 0..7
    const int i0 = (warpY * 4 + ty) * 8;         // 0..120 step 8
    const int j0 = (warpX * 8 + tx) * 4;         // 0..124 step 4

    const float* adjb = adj + (size_t)b * NP * NP;

    // ---------- Phase A: transpose adj into AD (AD[n][i] = adj[i][n]) ----------
    {
        float* stg = Xs + warp * (32 * 33);   // per-warp 32x33 staging (16*1056 = 16896 fits Xs)
        int ti = warp >> 2, tj = warp & 3;    // one 32x32 tile per warp
        // fill: coalesced global float4 read, SCALAR smem stores
#pragma unroll
        for (int s = 0; s < 8; ++s) {
            int r  = s * 4 + (lane >> 3);
            int c4 = lane & 7;
            float4 v = *(const float4*)(adjb + (ti * 32 + r) * NP + tj * 32 + c4 * 4);
            float* d = stg + r * 33 + c4 * 4;
            d[0] = v.x; d[1] = v.y; d[2] = v.z; d[3] = v.w;
        }
        __syncwarp();
        // drain transposed: conflict-free (33-pad) LDS + scalar STS
#pragma unroll
        for (int n2 = 0; n2 < 32; ++n2) {
            AD[(tj * 32 + n2) * RL + ti * 32 + lane] = stg[lane * 33 + n2];
        }
        __syncwarp();
    }

    // ---------- Phase B: x0T into Ys, W_in into WS, mask ----------
    if (tid < 128) {
        int n = tid;
        float4 f0 = *(const float4*)(feat + ((size_t)b * NP + n) * 8);
        float4 f1 = *(const float4*)(feat + ((size_t)b * NP + n) * 8 + 4);
        Ys[0 * RL + n] = f0.x; Ys[1 * RL + n] = f0.y;
        Ys[2 * RL + n] = f0.z; Ys[3 * RL + n] = f0.w;
        Ys[4 * RL + n] = f1.x; Ys[5 * RL + n] = f1.y;
        Ys[6 * RL + n] = f1.z; Ys[7 * RL + n] = f1.w;
        MSK[n] = mask[(size_t)b * NP + n];
    } else if (tid < 256) {
        int n = tid - 128;
        int p = pdg[(size_t)b * NP + n];
        float4 e0 = *(const float4*)(emb + p * 8);
        float4 e1 = *(const float4*)(emb + p * 8 + 4);
        Ys[ 8 * RL + n] = e0.x; Ys[ 9 * RL + n] = e0.y;
        Ys[10 * RL + n] = e0.z; Ys[11 * RL + n] = e0.w;
        Ys[12 * RL + n] = e1.x; Ys[13 * RL + n] = e1.y;
        Ys[14 * RL + n] = e1.z; Ys[15 * RL + n] = e1.w;
    }
    // W_in (16x128 = 2048 floats) into WS buf0: one float4 per thread
    *(float4*)(WS + tid * 4) = *(const float4*)(W_in + tid * 4);
    __syncthreads();

    // denom = max(sum(mask), 1)  (warp 0)
    if (warp == 0) {
        float s = MSK[lane] + MSK[lane + 32] + MSK[lane + 64] + MSK[lane + 96];
#pragma unroll
        for (int o = 16; o; o >>= 1) s += __shfl_down_sync(0xffffffffu, s, o);
        if (lane == 0) RED[7] = fmaxf(s, 1.0f);
    }

    unsigned long long acc[4][4];

    // ---------- Input GEMM: Xs[u][n] = sum_c W_in[c][u] * x0T[c][n] + b_in[u] ----------
    // C[i=u][j=n], A=WS, B=Ys(x0T), bias over i.
    zero_acc(acc);
#pragma unroll 8
    for (int k = 0; k < 16; ++k)
        mk_step(WS, UN, Ys, RL, k, i0, j0, acc);
    {
        float4 bi0 = *(const float4*)(b_in + i0);
        float4 bi1 = *(const float4*)(b_in + i0 + 4);
        float bia[8] = {bi0.x, bi0.y, bi0.z, bi0.w, bi1.x, bi1.y, bi1.z, bi1.w};
#pragma unroll
        for (int p = 0; p < 4; ++p) {
            float2 q0 = unpack2(acc[0][p]);
            float2 q1 = unpack2(acc[1][p]);
            float2 q2 = unpack2(acc[2][p]);
            float2 q3 = unpack2(acc[3][p]);
            float bl = bia[2 * p], bh = bia[2 * p + 1];
            *(float4*)(Xs + (i0 + 2 * p)     * RL + j0) = make_float4(q0.x + bl, q1.x + bl, q2.x + bl, q3.x + bl);
            *(float4*)(Xs + (i0 + 2 * p + 1) * RL + j0) = make_float4(q0.y + bh, q1.y + bh, q2.y + bh, q3.y + bh);
        }
    }
    __syncthreads();

    // ---------- Hidden layers ----------
#pragma unroll 1
    for (int l = 0; l < NHID; ++l) {
        const float* Wl  = W_h + l * UN * UN;
        const float* bhl = b_h + l * UN;

        // stage chunk 0 (2048 floats, one float4 per thread)
        *(float4*)(WS + tid * 4) = *(const float4*)(Wl + tid * 4);
        zero_acc(acc);
        __syncthreads();

        // GEMM1: Ys[n][u] = relu(sum_c Xs[c][n] * W[c][u] + b[u])
        // C[i=n][j=u], A=Xs(xT), B=WS, bias over j. W double-buffered.
#pragma unroll 1
        for (int c = 0; c < 8; ++c) {
            float4 p0;
            if (c < 7) p0 = *(const float4*)(Wl + (c + 1) * 2048 + tid * 4);
            const float* wsb = WS + (c & 1) * 2048;
            const float* xk  = Xs + c * 16 * RL;
#pragma unroll 8
            for (int kk = 0; kk < 16; ++kk)
                mk_step(xk, RL, wsb, UN, kk, i0, j0, acc);
            if (c < 7) {
                *(float4*)(WS + ((c + 1) & 1) * 2048 + tid * 4) = p0;
                __syncthreads();
            }
        }
        {
            float4 bj = *(const float4*)(bhl + j0);
#pragma unroll
            for (int p = 0; p < 4; ++p) {
                float2 q0 = unpack2(acc[0][p]);
                float2 q1 = unpack2(acc[1][p]);
                float2 q2 = unpack2(acc[2][p]);
                float2 q3 = unpack2(acc[3][p]);
                *(float4*)(Ys + (i0 + 2 * p) * RL + j0) =
                    make_float4(fmaxf(q0.x + bj.x, 0.f), fmaxf(q1.x + bj.y, 0.f),
                                fmaxf(q2.x + bj.z, 0.f), fmaxf(q3.x + bj.w, 0.f));
                *(float4*)(Ys + (i0 + 2 * p + 1) * RL + j0) =
                    make_float4(fmaxf(q0.y + bj.x, 0.f), fmaxf(q1.y + bj.y, 0.f),
                                fmaxf(q2.y + bj.z, 0.f), fmaxf(q3.y + bj.w, 0.f));
            }
        }
        __syncthreads();

        // GEMM2: Xs[u][i] = sum_n Ys[n][u] * AD[n][i]
        // C[i=u][j=particle], A=Ys, B=AD.
        zero_acc(acc);
#pragma unroll 8
        for (int k = 0; k < NP; ++k)
            mk_step(Ys, RL, AD, RL, k, i0, j0, acc);
#pragma unroll
        for (int p = 0; p < 4; ++p) {
            float2 q0 = unpack2(acc[0][p]);
            float2 q1 = unpack2(acc[1][p]);
            float2 q2 = unpack2(acc[2][p]);
            float2 q3 = unpack2(acc[3][p]);
            *(float4*)(Xs + (i0 + 2 * p)     * RL + j0) = make_float4(q0.x, q1.x, q2.x, q3.x);
            *(float4*)(Xs + (i0 + 2 * p + 1) * RL + j0) = make_float4(q0.y, q1.y, q2.y, q3.y);
        }
        __syncthreads();
    }

    // ---------- Masked mean pool + output projection ----------
    {
        int u = tid & 127;
        int h = tid >> 7;          // 0..3
        float s = 0.f;
#pragma unroll 8
        for (int i2 = 0; i2 < 32; ++i2) {
            int i = h * 32 + i2;
            s += Xs[u * RL + i] * MSK[i];
        }
        Ys[h * 128 + u] = s;       // Ys reused as scratch (512 floats)
    }
    __syncthreads();
    if (tid < 128) {
        float pooled = (Ys[tid] + Ys[128 + tid] + Ys[256 + tid] + Ys[384 + tid]) / RED[7];
        float v = pooled * W_out[tid];
#pragma unroll
        for (int o = 16; o; o >>= 1) v += __shfl_down_sync(0xffffffffu, v, o);
        if ((tid & 31) == 0) RED[tid >> 5] = v;
    }
    __syncthreads();
    if (tid == 0) out[b] = RED[0] + RED[1] + RED[2] + RED[3] + b_out[0];
}

extern "C" void kernel_launch(void* const* d_in, const int* in_sizes, int n_in,
                              void* d_out, int out_size)
{
    const int*   pdg   = (const int*)  d_in[0];
    const float* feat  = (const float*)d_in[1];
    const float* adjp  = (const float*)d_in[2];
    const float* maskp = (const float*)d_in[3];
    const float* emb   = (const float*)d_in[4];
    const float* W_in  = (const float*)d_in[5];
    const float* b_in  = (const float*)d_in[6];
    const float* W_h   = (const float*)d_in[7];
    const float* b_h   = (const float*)d_in[8];
    const float* W_out = (const float*)d_in[9];
    const float* b_out = (const float*)d_in[10];
    float* out = (float*)d_out;

    const int B = in_sizes[0] / NP;   // pdg has B*N elements

    cudaFuncSetAttribute(gcn_fused_kernel,
                         cudaFuncAttributeMaxDynamicSharedMemorySize, SMEM_BYTES);
    gcn_fused_kernel<<<B, NTHREADS, SMEM_BYTES>>>(
        pdg, feat, adjp, maskp, emb, W_in, b_in, W_h, b_h, W_out, b_out, out);
}

// round 8
// speedup vs baseline: 2.2266x; 2.2266x over previous
#include <cuda_runtime.h>
#include <cstdint>

#define RL   132
#define NTH  512
#define NHID 6

// float offsets in dynamic smem
#define F_ADJ  0                 // 128*132 adj row-major (A of GEMM2)
#define F_ACT  16896             // 128*132 X / Y^T / X' multiplexed
#define F_WT   33792             // 128*132 W^T[u][c] (B of GEMM1)
#define F_X0   50688             // 128*16 input features (A of input GEMM)
#define F_WINT 52736             // 128*24 W_in^T (B of input GEMM)
#define F_BIN  55808             // 128
#define F_BIA  55936             // 768
#define F_MSK  56704             // 128
#define F_WO   56832             // 128
#define F_PART 56960             // 512
#define F_RED  57472             // 8 (RED[7] = denom)
#define F_BOUT 57480
#define SMEM_FLOATS 57488
#define SMEM_BYTES  (SMEM_FLOATS * 4)

__device__ __forceinline__ uint32_t smem_u32(const void* p) {
    uint32_t a;
    asm("{ .reg .u64 t; cvta.to.shared.u64 t, %1; cvt.u32.u64 %0, t; }" : "=r"(a) : "l"(p));
    return a;
}

__device__ __forceinline__ float tf32r(float x) {
    float y;
    asm("cvt.rna.tf32.f32 %0, %1;" : "=f"(y) : "f"(x));
    return y;
}

__device__ __forceinline__ void ldsm4(uint32_t addr, uint32_t& r0, uint32_t& r1,
                                      uint32_t& r2, uint32_t& r3) {
    asm volatile("ldmatrix.sync.aligned.m8n8.x4.shared.b16 {%0,%1,%2,%3}, [%4];"
                 : "=r"(r0), "=r"(r1), "=r"(r2), "=r"(r3) : "r"(addr));
}

__device__ __forceinline__ void mma8(float* d,
                                     uint32_t a0, uint32_t a1, uint32_t a2, uint32_t a3,
                                     uint32_t b0, uint32_t b1) {
    asm volatile("mma.sync.aligned.m16n8k8.row.col.f32.tf32.tf32.f32 "
                 "{%0,%1,%2,%3}, {%4,%5,%6,%7}, {%8,%9}, {%0,%1,%2,%3};"
                 : "+f"(d[0]), "+f"(d[1]), "+f"(d[2]), "+f"(d[3])
                 : "r"(a0), "r"(a1), "r"(a2), "r"(a3), "r"(b0), "r"(b1));
}

__device__ __forceinline__ void zero_acc(float (&acc)[2][4][4]) {
#pragma unroll
    for (int i = 0; i < 2; ++i)
#pragma unroll
        for (int j = 0; j < 4; ++j)
#pragma unroll
            for (int q = 0; q < 4; ++q) acc[i][j][q] = 0.0f;
}

// 128x128x128 GEMM: A row-major [m][k] stride RL at aA0/aA1 (two m16 halves),
// B^T row-major [n][k] stride RL at aB0/aB1. Optional W[l+1] prefetch into WT.
template<bool PREF>
__device__ __forceinline__ void gemm128(uint32_t aA0, uint32_t aA1,
                                        uint32_t aB0, uint32_t aB1,
                                        float (&acc)[2][4][4],
                                        const float* __restrict__ wg,
                                        float* __restrict__ smf,
                                        int cOffW, int j4) {
    float4 wb[4];
    if (PREF) {
#pragma unroll
        for (int q = 0; q < 4; ++q)
            wb[q] = *(const float4*)(wg + (q * 16 + cOffW) * 128 + j4 * 4);
    }
#pragma unroll
    for (int k = 0; k < 16; ++k) {
        uint32_t a0,a1,a2,a3,a4,a5,a6,a7, r0,r1,r2,r3, s0,s1,s2,s3;
        ldsm4(aA0 + k * 32, a0, a1, a2, a3);
        ldsm4(aA1 + k * 32, a4, a5, a6, a7);
        ldsm4(aB0 + k * 32, r0, r1, r2, r3);
        ldsm4(aB1 + k * 32, s0, s1, s2, s3);
        mma8(acc[0][0], a0, a1, a2, a3, r0, r2);
        mma8(acc[0][1], a0, a1, a2, a3, r1, r3);
        mma8(acc[0][2], a0, a1, a2, a3, s0, s2);
        mma8(acc[0][3], a0, a1, a2, a3, s1, s3);
        mma8(acc[1][0], a4, a5, a6, a7, r0, r2);
        mma8(acc[1][1], a4, a5, a6, a7, r1, r3);
        mma8(acc[1][2], a4, a5, a6, a7, s0, s2);
        mma8(acc[1][3], a4, a5, a6, a7, s1, s3);
        if (PREF && (k & 1)) {
            int s = k >> 1;                       // 0..7
            int c = s * 16 + cOffW;
            float4 v = wb[s & 3];
            smf[F_WT + (j4 * 4 + 0) * RL + c] = tf32r(v.x);
            smf[F_WT + (j4 * 4 + 1) * RL + c] = tf32r(v.y);
            smf[F_WT + (j4 * 4 + 2) * RL + c] = tf32r(v.z);
            smf[F_WT + (j4 * 4 + 3) * RL + c] = tf32r(v.w);
            if (s < 4)
                wb[s & 3] = *(const float4*)(wg + ((s + 4) * 16 + cOffW) * 128 + j4 * 4);
        }
    }
}

__global__ __launch_bounds__(NTH, 1)
void gcn_mma_kernel(const int* __restrict__ pdg,
                    const float* __restrict__ feat,
                    const float* __restrict__ adj,
                    const float* __restrict__ mask,
                    const float* __restrict__ emb,
                    const float* __restrict__ W_in,
                    const float* __restrict__ b_in,
                    const float* __restrict__ W_h,
                    const float* __restrict__ b_h,
                    const float* __restrict__ W_out,
                    const float* __restrict__ b_out,
                    float* __restrict__ out)
{
    extern __shared__ float smf[];
    const uint32_t SB = smem_u32(smf);

    const int b    = blockIdx.x;
    const int tid  = threadIdx.x;
    const int lane = tid & 31;
    const int warp = tid >> 5;
    const int m0 = (warp >> 2) * 32;
    const int n0 = (warp & 3) * 32;

    // ldmatrix per-thread segment pattern (quadrant q = lane>>3)
    const int aRow   = (lane & 7) + ((lane >> 3) & 1) * 8;
    const int aCol16 = lane >> 4;
    const uint32_t fragOff = (uint32_t)(aRow * RL) * 4 + (uint32_t)aCol16 * 16;

    // W-transpose staging pattern
    const int cOffW = (warp >> 3) * 8 + (lane & 7);
    const int j4    = (warp & 7) * 4 + (lane >> 3);

    // epilogue pattern
    const int er = lane >> 2;
    const int ec = (lane & 3) * 2;

    const float* adjb = adj + (size_t)b * 16384;

    // ================= staging =================
#pragma unroll
    for (int i = 0; i < 8; ++i) {             // adj -> ADJ (cvt)
        int idx = i * 512 + tid;
        int row = idx >> 5, c4 = idx & 31;
        float4 v = *(const float4*)(adjb + row * 128 + c4 * 4);
        float4 w = make_float4(tf32r(v.x), tf32r(v.y), tf32r(v.z), tf32r(v.w));
        *(float4*)&smf[F_ADJ + row * RL + c4 * 4] = w;
    }
    {                                          // W_h[0]^T -> WT (cvt)
        float4 wa[4];
#pragma unroll
        for (int b2 = 0; b2 < 2; ++b2) {
#pragma unroll
            for (int q = 0; q < 4; ++q) {
                int c = (b2 * 4 + q) * 16 + cOffW;
                wa[q] = *(const float4*)(W_h + c * 128 + j4 * 4);
            }
#pragma unroll
            for (int q = 0; q < 4; ++q) {
                int c = (b2 * 4 + q) * 16 + cOffW;
                smf[F_WT + (j4 * 4 + 0) * RL + c] = tf32r(wa[q].x);
                smf[F_WT + (j4 * 4 + 1) * RL + c] = tf32r(wa[q].y);
                smf[F_WT + (j4 * 4 + 2) * RL + c] = tf32r(wa[q].z);
                smf[F_WT + (j4 * 4 + 3) * RL + c] = tf32r(wa[q].w);
            }
        }
    }
    if (tid < 128) {                           // x0 -> X0 (cvt)
        int p = tid;
        float4 f0 = *(const float4*)(feat + ((size_t)b * 128 + p) * 8);
        float4 f1 = *(const float4*)(feat + ((size_t)b * 128 + p) * 8 + 4);
        int pg = pdg[(size_t)b * 128 + p];
        float4 e0 = *(const float4*)(emb + pg * 8);
        float4 e1 = *(const float4*)(emb + pg * 8 + 4);
        float vv[16] = {f0.x,f0.y,f0.z,f0.w, f1.x,f1.y,f1.z,f1.w,
                        e0.x,e0.y,e0.z,e0.w, e1.x,e1.y,e1.z,e1.w};
#pragma unroll
        for (int j = 0; j < 16; ++j) smf[F_X0 + p * 16 + j] = tf32r(vv[j]);
    }
    {                                          // W_in^T -> WINT (cvt)
        int c = tid >> 5, u0 = (tid * 4) & 127;
        float4 wv = *(const float4*)(W_in + tid * 4);
        smf[F_WINT + (u0 + 0) * 24 + c] = tf32r(wv.x);
        smf[F_WINT + (u0 + 1) * 24 + c] = tf32r(wv.y);
        smf[F_WINT + (u0 + 2) * 24 + c] = tf32r(wv.z);
        smf[F_WINT + (u0 + 3) * 24 + c] = tf32r(wv.w);
    }
    if (tid < 32) {
        *(float4*)&smf[F_BIN + tid * 4] = *(const float4*)(b_in + tid * 4);
    } else if (tid < 224) {
        int q = tid - 32;
        *(float4*)&smf[F_BIA + q * 4] = *(const float4*)(b_h + q * 4);
    } else if (tid < 256) {
        int q = tid - 224;
        *(float4*)&smf[F_MSK + q * 4] = *(const float4*)(mask + (size_t)b * 128 + q * 4);
    } else if (tid < 288) {
        int q = tid - 256;
        *(float4*)&smf[F_WO + q * 4] = *(const float4*)(W_out + q * 4);
    } else if (tid == 288) {
        smf[F_BOUT] = b_out[0];
    }
    __syncthreads();

    if (warp == 0) {                           // denom
        float s = smf[F_MSK + lane] + smf[F_MSK + lane + 32]
                + smf[F_MSK + lane + 64] + smf[F_MSK + lane + 96];
#pragma unroll
        for (int o = 16; o; o >>= 1) s += __shfl_down_sync(0xffffffffu, s, o);
        if (lane == 0) smf[F_RED + 7] = fmaxf(s, 1.0f);
    }

    float acc[2][4][4];

    // ================= input GEMM: X = x0 @ W_in + b_in (K=16) =================
    zero_acc(acc);
    {
        uint32_t xA0 = SB + F_X0 * 4 + (uint32_t)((m0 + aRow) * 16) * 4 + (uint32_t)aCol16 * 16;
        uint32_t xA1 = xA0 + 16u * 16u * 4u;
        uint32_t wB0 = SB + F_WINT * 4 + (uint32_t)((n0 + aRow) * 24) * 4 + (uint32_t)aCol16 * 16;
        uint32_t wB1 = wB0 + 16u * 24u * 4u;
#pragma unroll
        for (int k = 0; k < 2; ++k) {
            uint32_t a0,a1,a2,a3,a4,a5,a6,a7, r0,r1,r2,r3, s0,s1,s2,s3;
            ldsm4(xA0 + k * 32, a0, a1, a2, a3);
            ldsm4(xA1 + k * 32, a4, a5, a6, a7);
            ldsm4(wB0 + k * 32, r0, r1, r2, r3);
            ldsm4(wB1 + k * 32, s0, s1, s2, s3);
            mma8(acc[0][0], a0,a1,a2,a3, r0, r2);
            mma8(acc[0][1], a0,a1,a2,a3, r1, r3);
            mma8(acc[0][2], a0,a1,a2,a3, s0, s2);
            mma8(acc[0][3], a0,a1,a2,a3, s1, s3);
            mma8(acc[1][0], a4,a5,a6,a7, r0, r2);
            mma8(acc[1][1], a4,a5,a6,a7, r1, r3);
            mma8(acc[1][2], a4,a5,a6,a7, s0, s2);
            mma8(acc[1][3], a4,a5,a6,a7, s1, s3);
        }
    }
    // epilogue: + b_in, cvt, store X row-major into ACT
#pragma unroll
    for (int mt = 0; mt < 2; ++mt)
#pragma unroll
        for (int nt = 0; nt < 4; ++nt) {
            int p0 = m0 + mt * 16 + er;
            int u0 = n0 + nt * 8 + ec;
            float bi0 = smf[F_BIN + u0], bi1 = smf[F_BIN + u0 + 1];
            *(float2*)&smf[F_ACT + p0 * RL + u0] =
                make_float2(tf32r(acc[mt][nt][0] + bi0), tf32r(acc[mt][nt][1] + bi1));
            *(float2*)&smf[F_ACT + (p0 + 8) * RL + u0] =
                make_float2(tf32r(acc[mt][nt][2] + bi0), tf32r(acc[mt][nt][3] + bi1));
        }
    __syncthreads();

    // ================= hidden layers =================
    const uint32_t actB = SB + F_ACT * 4;
    const uint32_t adjB = SB + F_ADJ * 4;
    const uint32_t wtB  = SB + F_WT * 4;

#pragma unroll 1
    for (int l = 0; l < NHID; ++l) {
        // GEMM1: Y[p][u] = X @ W_h[l]
        zero_acc(acc);
        {
            uint32_t aA0 = actB + (uint32_t)(m0 * RL) * 4 + fragOff;
            uint32_t aB0 = wtB  + (uint32_t)(n0 * RL) * 4 + fragOff;
            gemm128<false>(aA0, aA0 + 16u * RL * 4u, aB0, aB0 + 16u * RL * 4u,
                           acc, nullptr, smf, cOffW, j4);
        }
        __syncthreads();
        // epi1: relu(+bias), cvt, store Y^T into ACT
#pragma unroll
        for (int nt = 0; nt < 4; ++nt) {
            int u0 = n0 + nt * 8 + ec;
            float bi0 = smf[F_BIA + l * 128 + u0];
            float bi1 = smf[F_BIA + l * 128 + u0 + 1];
#pragma unroll
            for (int mt = 0; mt < 2; ++mt) {
                int p0 = m0 + mt * 16 + er;
                smf[F_ACT + u0 * RL + p0]           = tf32r(fmaxf(acc[mt][nt][0] + bi0, 0.0f));
                smf[F_ACT + (u0 + 1) * RL + p0]     = tf32r(fmaxf(acc[mt][nt][1] + bi1, 0.0f));
                smf[F_ACT + u0 * RL + p0 + 8]       = tf32r(fmaxf(acc[mt][nt][2] + bi0, 0.0f));
                smf[F_ACT + (u0 + 1) * RL + p0 + 8] = tf32r(fmaxf(acc[mt][nt][3] + bi1, 0.0f));
            }
        }
        __syncthreads();

        // GEMM2: X'[p][u] = adj @ Y   (+ prefetch W_h[l+1] into WT)
        zero_acc(acc);
        {
            uint32_t aA0 = adjB + (uint32_t)(m0 * RL) * 4 + fragOff;
            uint32_t aB0 = actB + (uint32_t)(n0 * RL) * 4 + fragOff;
            if (l + 1 < NHID)
                gemm128<true>(aA0, aA0 + 16u * RL * 4u, aB0, aB0 + 16u * RL * 4u,
                              acc, W_h + (size_t)(l + 1) * 16384, smf, cOffW, j4);
            else
                gemm128<false>(aA0, aA0 + 16u * RL * 4u, aB0, aB0 + 16u * RL * 4u,
                               acc, nullptr, smf, cOffW, j4);
        }
        __syncthreads();
        // epi2: store X' row-major into ACT (cvt unless last layer)
        const bool last = (l == NHID - 1);
#pragma unroll
        for (int mt = 0; mt < 2; ++mt)
#pragma unroll
            for (int nt = 0; nt < 4; ++nt) {
                int p0 = m0 + mt * 16 + er;
                int u0 = n0 + nt * 8 + ec;
                float v0 = acc[mt][nt][0], v1 = acc[mt][nt][1];
                float v2 = acc[mt][nt][2], v3 = acc[mt][nt][3];
                if (!last) { v0 = tf32r(v0); v1 = tf32r(v1); v2 = tf32r(v2); v3 = tf32r(v3); }
                *(float2*)&smf[F_ACT + p0 * RL + u0]       = make_float2(v0, v1);
                *(float2*)&smf[F_ACT + (p0 + 8) * RL + u0] = make_float2(v2, v3);
            }
        __syncthreads();
    }

    // ================= masked mean pool + output projection =================
    {
        int u = tid & 127;
        int h = tid >> 7;
        float s = 0.0f;
#pragma unroll 8
        for (int i = 0; i < 32; ++i) {
            int p = h * 32 + i;
            s += smf[F_ACT + p * RL + u] * smf[F_MSK + p];
        }
        smf[F_PART + h * 128 + u] = s;
    }
    __syncthreads();
    if (tid < 128) {
        float pooled = (smf[F_PART + tid] + smf[F_PART + 128 + tid]
                      + smf[F_PART + 256 + tid] + smf[F_PART + 384 + tid]) / smf[F_RED + 7];
        float v = pooled * smf[F_WO + tid];
#pragma unroll
        for (int o = 16; o; o >>= 1) v += __shfl_down_sync(0xffffffffu, v, o);
        if ((tid & 31) == 0) smf[F_RED + (tid >> 5)] = v;
    }
    __syncthreads();
    if (tid == 0)
        out[b] = smf[F_RED + 0] + smf[F_RED + 1] + smf[F_RED + 2] + smf[F_RED + 3]
               + smf[F_BOUT];
}

extern "C" void kernel_launch(void* const* d_in, const int* in_sizes, int n_in,
                              void* d_out, int out_size)
{
    const int*   pdg   = (const int*)  d_in[0];
    const float* feat  = (const float*)d_in[1];
    const float* adjp  = (const float*)d_in[2];
    const float* maskp = (const float*)d_in[3];
    const float* emb   = (const float*)d_in[4];
    const float* W_in  = (const float*)d_in[5];
    const float* b_in  = (const float*)d_in[6];
    const float* W_h   = (const float*)d_in[7];
    const float* b_h   = (const float*)d_in[8];
    const float* W_out = (const float*)d_in[9];
    const float* b_out = (const float*)d_in[10];
    float* out = (float*)d_out;

    const int B = in_sizes[0] / 128;

    cudaFuncSetAttribute(gcn_mma_kernel,
                         cudaFuncAttributeMaxDynamicSharedMemorySize, SMEM_BYTES);
    gcn_mma_kernel<<<B, NTH, SMEM_BYTES>>>(
        pdg, feat, adjp, maskp, emb, W_in, b_in, W_h, b_h, W_out, b_out, out);
}